// round 2
// baseline (speedup 1.0000x reference)
#include <cuda_runtime.h>
#include <math.h>

#define E_    2048
#define S_    256
#define Q_    25
#define NN_   36
#define R_    15
#define H_    128
#define K2_   72           // 2*NN_
#define SR_   3840         // S_*R_
#define NPTS  (E_*NN_)     // 73728
#define MLP_BLOCKS (NPTS/128)  // 576
#define GX 30
#define GY 16
#define NPART (GX*GY)

// ---- scratch (no allocations allowed) ----
__device__ float g_evcat[E_*K2_];      // [E][72] = [cx*ev | cy*ev]
__device__ float g_Acat[SR_*K2_];      // [s*R+r][72]
__device__ float g_partial[NPART];
__device__ unsigned g_count = 0;

// ---- packed f32x2 helpers ----
typedef unsigned long long u64t;
__device__ __forceinline__ u64t pk2(float lo, float hi){
    u64t r; asm("mov.b64 %0,{%1,%2};" : "=l"(r) : "f"(lo), "f"(hi)); return r;
}
__device__ __forceinline__ u64t fma2(u64t a, u64t b, u64t c){
    u64t d; asm("fma.rn.f32x2 %0,%1,%2,%3;" : "=l"(d) : "l"(a), "l"(b), "l"(c)); return d;
}
__device__ __forceinline__ void upk2(u64t x, float& lo, float& hi){
    asm("mov.b64 {%0,%1},%2;" : "=f"(lo), "=f"(hi) : "l"(x));
}

union F4U { float4 f; u64t u[2]; };

// fast tanh: 1 - 2/(exp(2x)+1), 2 MUFU + few ALU, ~3e-7 abs error
__device__ __forceinline__ float fast_tanh(float x){
    float e;
    asm("ex2.approx.f32 %0, %1;" : "=f"(e) : "f"(x * 2.885390081777926f)); // 2*log2(e)
    float r;
    asm("rcp.approx.f32 %0, %1;" : "=f"(r) : "f"(e + 1.0f));
    return 1.0f - 2.0f * r;
}

// ============================================================
// Kernel 1: Acat[s,r,n] = sum_q w[q]*Base[q,r]*I[s,q,n]
// ============================================================
__global__ void build_acat(const float* __restrict__ Ixx, const float* __restrict__ Iyy,
                           const float* __restrict__ wq,  const float* __restrict__ Base){
    __shared__ float WB[Q_*R_];
    __shared__ float sI0[Q_*NN_];
    __shared__ float sI1[Q_*NN_];
    const int s = blockIdx.x, tid = threadIdx.x;

    for (int i = tid; i < Q_*R_; i += blockDim.x){
        int q = i / R_, r = i - q*R_;
        WB[i] = wq[q] * Base[q*R_ + r];
    }
    for (int i = tid; i < Q_*NN_; i += blockDim.x){
        sI0[i] = Ixx[s*Q_*NN_ + i];
        sI1[i] = Iyy[s*Q_*NN_ + i];
    }
    __syncthreads();

    for (int idx = tid; idx < R_*K2_; idx += blockDim.x){
        int r = idx / K2_, n = idx - r*K2_;
        const float* I = (n < NN_) ? sI0 : sI1;
        int nn = (n < NN_) ? n : (n - NN_);
        float acc = 0.f;
        #pragma unroll
        for (int q = 0; q < Q_; q++) acc += WB[q*R_ + r] * I[q*NN_ + nn];
        g_Acat[(s*R_ + r)*K2_ + n] = acc;
    }
}

// ============================================================
// MLP layer: Hout[j][p] = tanh(sum_k Hin[k][p]*W[k][j] + b[j])
// ============================================================
__device__ __forceinline__ void gemm_layer(const float* __restrict__ Hin, float* __restrict__ Hout,
                                           const float* __restrict__ W, const float* __restrict__ b){
    const int tid = threadIdx.x;
    const int tx = tid & 15, ty = tid >> 4;
    const int m0 = ty * 8, n0 = tx * 8;

    u64t acc[8][4];
    #pragma unroll
    for (int jp = 0; jp < 4; jp++){
        u64t bb = pk2(__ldg(&b[n0 + 2*jp]), __ldg(&b[n0 + 2*jp + 1]));
        #pragma unroll
        for (int i = 0; i < 8; i++) acc[i][jp] = bb;
    }

    for (int k = 0; k < H_; k++){
        float4 a0 = *(const float4*)(Hin + k*132 + m0);
        float4 a1 = *(const float4*)(Hin + k*132 + m0 + 4);
        F4U w0, w1;
        w0.f = __ldg((const float4*)(W + k*H_ + n0));
        w1.f = __ldg((const float4*)(W + k*H_ + n0 + 4));
        u64t bv[4] = { w0.u[0], w0.u[1], w1.u[0], w1.u[1] };
        float av[8] = { a0.x, a0.y, a0.z, a0.w, a1.x, a1.y, a1.z, a1.w };
        #pragma unroll
        for (int i = 0; i < 8; i++){
            u64t ad = pk2(av[i], av[i]);
            #pragma unroll
            for (int jp = 0; jp < 4; jp++) acc[i][jp] = fma2(ad, bv[jp], acc[i][jp]);
        }
    }

    #pragma unroll
    for (int i = 0; i < 8; i++){
        #pragma unroll
        for (int jp = 0; jp < 4; jp++){
            float lo, hi; upk2(acc[i][jp], lo, hi);
            Hout[(n0 + 2*jp    )*132 + m0 + i] = fast_tanh(lo);
            Hout[(n0 + 2*jp + 1)*132 + m0 + i] = fast_tanh(hi);
        }
    }
}

// ============================================================
// Kernel 2: MLP for 128 points/block -> evcat
// ============================================================
__global__ __launch_bounds__(256, 1)
void mlp_kernel(const float* __restrict__ nodes,
                const float* __restrict__ W1, const float* __restrict__ b1,
                const float* __restrict__ W2, const float* __restrict__ b2,
                const float* __restrict__ W3, const float* __restrict__ b3,
                const float* __restrict__ W4, const float* __restrict__ b4,
                const float* __restrict__ BDD){
    extern __shared__ float sm[];
    float* Ha = sm;               // [128][132]
    float* Hb = sm + 128*132;     // [128][132]
    __shared__ float xs[128][2];

    const int tid = threadIdx.x;
    const int p0 = blockIdx.x * 128;

    if (tid < 256) ((float*)xs)[tid] = nodes[p0*2 + tid];
    __syncthreads();

    // layer 1
    for (int idx = tid; idx < H_*128; idx += 256){
        int j = idx >> 7, p = idx & 127;
        float pre = xs[p][0]*__ldg(&W1[j]) + xs[p][1]*__ldg(&W1[H_ + j]) + __ldg(&b1[j]);
        Ha[j*132 + p] = fast_tanh(pre);
    }
    __syncthreads();

    gemm_layer(Ha, Hb, W2, b2);  __syncthreads();
    gemm_layer(Hb, Ha, W3, b3);  __syncthreads();

    // layer 4 + scale by (cx, cy), scatter into evcat
    if (tid < 128){
        float acc = 0.f;
        #pragma unroll 8
        for (int k = 0; k < H_; k++) acc += Ha[k*132 + tid] * __ldg(&W4[k]);
        float ev = acc + __ldg(&b4[0]);
        int p = p0 + tid;
        int e = p / NN_, n = p - e*NN_;
        float c00 = __ldg(&BDD[e*4 + 0]), c01 = __ldg(&BDD[e*4 + 1]);
        float c10 = __ldg(&BDD[e*4 + 2]), c11 = __ldg(&BDD[e*4 + 3]);
        g_evcat[e*K2_ + n]       = (c00 + c10) * ev;
        g_evcat[e*K2_ + NN_ + n] = (c01 + c11) * ev;
    }
}

// ============================================================
// Kernel 3: u[e,sr] = -J * (evcat @ Acat^T), fused loss + final reduce
// ============================================================
__global__ __launch_bounds__(256, 2)
void gemm_loss(const float* __restrict__ J, const float* __restrict__ F,
               float* __restrict__ out){
    extern __shared__ float sm[];
    float* As = sm;              // [72][132]
    float* Bs = sm + K2_*132;    // [72][132]
    const int tid = threadIdx.x;
    const int m0g = blockIdx.y * 128, n0g = blockIdx.x * 128;

    for (int idx = tid; idx < 128*K2_; idx += 256){
        int m = idx / K2_, k = idx - m*K2_;
        As[k*132 + m] = g_evcat[(m0g + m)*K2_ + k];
    }
    for (int idx = tid; idx < 128*K2_; idx += 256){
        int n = idx / K2_, k = idx - n*K2_;
        Bs[k*132 + n] = g_Acat[(n0g + n)*K2_ + k];
    }
    __syncthreads();

    const int tx = tid & 15, ty = tid >> 4;
    const int m0 = ty * 8, n0 = tx * 8;

    u64t acc[8][4];
    #pragma unroll
    for (int i = 0; i < 8; i++)
        #pragma unroll
        for (int jp = 0; jp < 4; jp++) acc[i][jp] = 0ULL;

    for (int k = 0; k < K2_; k++){
        float4 a0 = *(const float4*)(As + k*132 + m0);
        float4 a1 = *(const float4*)(As + k*132 + m0 + 4);
        F4U b0, b1;
        b0.f = *(const float4*)(Bs + k*132 + n0);
        b1.f = *(const float4*)(Bs + k*132 + n0 + 4);
        u64t bv[4] = { b0.u[0], b0.u[1], b1.u[0], b1.u[1] };
        float av[8] = { a0.x, a0.y, a0.z, a0.w, a1.x, a1.y, a1.z, a1.w };
        #pragma unroll
        for (int i = 0; i < 8; i++){
            u64t ad = pk2(av[i], av[i]);
            #pragma unroll
            for (int jp = 0; jp < 4; jp++) acc[i][jp] = fma2(ad, bv[jp], acc[i][jp]);
        }
    }

    // fused epilogue: u = -J*dot; res = u - F; accumulate res^2
    float lsum = 0.f;
    #pragma unroll
    for (int i = 0; i < 8; i++){
        int e = m0g + m0 + i;
        #pragma unroll
        for (int jp = 0; jp < 4; jp++){
            float lo, hi; upk2(acc[i][jp], lo, hi);
            int n  = n0g + n0 + 2*jp;
            float j0 = __ldg(&J[e*S_ + (n    )/R_]);
            float j1 = __ldg(&J[e*S_ + (n + 1)/R_]);
            float r0 = -j0*lo - __ldg(&F[e*SR_ + n    ]);
            float r1 = -j1*hi - __ldg(&F[e*SR_ + n + 1]);
            lsum += r0*r0 + r1*r1;
        }
    }

    __shared__ float red[256];
    red[tid] = lsum; __syncthreads();
    #pragma unroll
    for (int s = 128; s > 0; s >>= 1){
        if (tid < s) red[tid] += red[tid + s];
        __syncthreads();
    }

    __shared__ unsigned s_last;
    if (tid == 0){
        g_partial[blockIdx.y * GX + blockIdx.x] = red[0];
        __threadfence();
        unsigned t = atomicAdd(&g_count, 1u);
        s_last = (t == NPART - 1u) ? 1u : 0u;
    }
    __syncthreads();

    if (s_last){
        // deterministic final reduction (fixed order, double)
        __shared__ double dred[256];
        double s = 0.0;
        for (int i = tid; i < NPART; i += 256) s += (double)g_partial[i];
        dred[tid] = s; __syncthreads();
        #pragma unroll
        for (int k = 128; k > 0; k >>= 1){
            if (tid < k) dred[tid] += dred[tid + k];
            __syncthreads();
        }
        if (tid == 0){
            out[0] = (float)(dred[0] / (double)R_);
            g_count = 0;   // reset for next (graph-replayed) call
        }
    }
}

// ============================================================
extern "C" void kernel_launch(void* const* d_in, const int* in_sizes, int n_in,
                              void* d_out, int out_size){
    const float* nodes = (const float*)d_in[0];
    const float* W1    = (const float*)d_in[1];
    const float* b1    = (const float*)d_in[2];
    const float* W2    = (const float*)d_in[3];
    const float* b2    = (const float*)d_in[4];
    const float* W3    = (const float*)d_in[5];
    const float* b3    = (const float*)d_in[6];
    const float* W4    = (const float*)d_in[7];
    const float* b4    = (const float*)d_in[8];
    const float* Ixx   = (const float*)d_in[9];
    const float* Iyy   = (const float*)d_in[10];
    const float* BDD   = (const float*)d_in[11];
    const float* wq    = (const float*)d_in[12];
    const float* Base  = (const float*)d_in[13];
    const float* J     = (const float*)d_in[14];
    const float* F     = (const float*)d_in[15];

    const int mlp_smem  = 2 * 128 * 132 * 4;
    const int gemm_smem = 2 * K2_ * 132 * 4;
    cudaFuncSetAttribute(mlp_kernel, cudaFuncAttributeMaxDynamicSharedMemorySize, mlp_smem);
    cudaFuncSetAttribute(gemm_loss,  cudaFuncAttributeMaxDynamicSharedMemorySize, gemm_smem);

    build_acat<<<S_, 128>>>(Ixx, Iyy, wq, Base);
    mlp_kernel<<<MLP_BLOCKS, 256, mlp_smem>>>(nodes, W1, b1, W2, b2, W3, b3, W4, b4, BDD);
    gemm_loss<<<dim3(GX, GY), 256, gemm_smem>>>(J, F, (float*)d_out);
}

// round 3
// speedup vs baseline: 1.1160x; 1.1160x over previous
#include <cuda_runtime.h>
#include <math.h>

#define E_    2048
#define S_    256
#define Q_    25
#define NN_   36
#define R_    15
#define H_    128
#define K2_   72           // 2*NN_
#define SR_   3840         // S_*R_
#define NPTS  (E_*NN_)     // 73728
#define PPB   64           // points per MLP block
#define MLP_BLOCKS (NPTS/PPB)   // 1152
#define STAGE1_BLOCKS (MLP_BLOCKS + S_)  // 1408
#define GX 30              // N tiles (3840/128)
#define GY 32              // M tiles (2048/64)
#define NPART (GX*GY)      // 960

#define ASTRIDE 68         // 64 + 4 pad (16B aligned)
#define BSTRIDE 132        // 128 + 4 pad

// ---- scratch ----
__device__ float g_evcat[E_*K2_];
__device__ float g_Acat[SR_*K2_];
__device__ float g_partial[NPART];
__device__ unsigned g_count = 0;

// ---- packed f32x2 helpers ----
typedef unsigned long long u64t;
__device__ __forceinline__ u64t pk2(float lo, float hi){
    u64t r; asm("mov.b64 %0,{%1,%2};" : "=l"(r) : "f"(lo), "f"(hi)); return r;
}
__device__ __forceinline__ u64t fma2(u64t a, u64t b, u64t c){
    u64t d; asm("fma.rn.f32x2 %0,%1,%2,%3;" : "=l"(d) : "l"(a), "l"(b), "l"(c)); return d;
}
__device__ __forceinline__ void upk2(u64t x, float& lo, float& hi){
    asm("mov.b64 {%0,%1},%2;" : "=f"(lo), "=f"(hi) : "l"(x));
}
union F4U { float4 f; u64t u[2]; };

// fast tanh: 1 - 2/(exp(2x)+1)
__device__ __forceinline__ float fast_tanh(float x){
    float e;
    asm("ex2.approx.f32 %0, %1;" : "=f"(e) : "f"(x * 2.885390081777926f));
    float r;
    asm("rcp.approx.f32 %0, %1;" : "=f"(r) : "f"(e + 1.0f));
    return 1.0f - 2.0f * r;
}

// ============================================================
// MLP layer on 64 points: Hout[j][p] = tanh(sum_k Hin[k][p]*W[k][j]+b[j])
// 128 threads, 8x8 per thread. Hin/Hout smem [128][ASTRIDE].
// ============================================================
__device__ __forceinline__ void gemm_layer64(const float* __restrict__ Hin, float* __restrict__ Hout,
                                             const float* __restrict__ W, const float* __restrict__ b){
    const int tid = threadIdx.x;
    const int tx = tid & 15, ty = tid >> 4;   // tx: 16 (n), ty: 8 (m)
    const int m0 = ty * 8, n0 = tx * 8;

    u64t acc[8][4];
    #pragma unroll
    for (int jp = 0; jp < 4; jp++){
        u64t bb = pk2(__ldg(&b[n0 + 2*jp]), __ldg(&b[n0 + 2*jp + 1]));
        #pragma unroll
        for (int i = 0; i < 8; i++) acc[i][jp] = bb;
    }

    #pragma unroll 4
    for (int k = 0; k < H_; k++){
        float4 a0 = *(const float4*)(Hin + k*ASTRIDE + m0);
        float4 a1 = *(const float4*)(Hin + k*ASTRIDE + m0 + 4);
        F4U w0, w1;
        w0.f = __ldg((const float4*)(W + k*H_ + n0));
        w1.f = __ldg((const float4*)(W + k*H_ + n0 + 4));
        u64t bv[4] = { w0.u[0], w0.u[1], w1.u[0], w1.u[1] };
        float av[8] = { a0.x, a0.y, a0.z, a0.w, a1.x, a1.y, a1.z, a1.w };
        #pragma unroll
        for (int i = 0; i < 8; i++){
            u64t ad = pk2(av[i], av[i]);
            #pragma unroll
            for (int jp = 0; jp < 4; jp++) acc[i][jp] = fma2(ad, bv[jp], acc[i][jp]);
        }
    }

    #pragma unroll
    for (int i = 0; i < 8; i++){
        #pragma unroll
        for (int jp = 0; jp < 4; jp++){
            float lo, hi; upk2(acc[i][jp], lo, hi);
            Hout[(n0 + 2*jp    )*ASTRIDE + m0 + i] = fast_tanh(lo);
            Hout[(n0 + 2*jp + 1)*ASTRIDE + m0 + i] = fast_tanh(hi);
        }
    }
}

// ============================================================
// Stage 1: blocks [0,1152) run MLP on 64 points each;
//          blocks [1152,1408) build Acat for one s each.
// ============================================================
__global__ __launch_bounds__(128, 3)
void stage1(const float* __restrict__ nodes,
            const float* __restrict__ W1, const float* __restrict__ b1,
            const float* __restrict__ W2, const float* __restrict__ b2,
            const float* __restrict__ W3, const float* __restrict__ b3,
            const float* __restrict__ W4, const float* __restrict__ b4,
            const float* __restrict__ BDD,
            const float* __restrict__ Ixx, const float* __restrict__ Iyy,
            const float* __restrict__ wq,  const float* __restrict__ Base){
    extern __shared__ float sm[];
    const int tid = threadIdx.x;

    if (blockIdx.x >= MLP_BLOCKS){
        // ---------- build_acat branch ----------
        const int s = blockIdx.x - MLP_BLOCKS;
        float* WB  = sm;                    // [Q][R]
        float* sI0 = WB  + Q_*R_;           // [Q][NN]
        float* sI1 = sI0 + Q_*NN_;          // [Q][NN]

        for (int i = tid; i < Q_*R_; i += 128){
            int q = i / R_, r = i - q*R_;
            WB[i] = wq[q] * Base[q*R_ + r];
        }
        for (int i = tid; i < Q_*NN_; i += 128){
            sI0[i] = Ixx[s*Q_*NN_ + i];
            sI1[i] = Iyy[s*Q_*NN_ + i];
        }
        __syncthreads();

        for (int idx = tid; idx < R_*K2_; idx += 128){
            int r = idx / K2_, n = idx - r*K2_;
            const float* I = (n < NN_) ? sI0 : sI1;
            int nn = (n < NN_) ? n : (n - NN_);
            float acc = 0.f;
            #pragma unroll
            for (int q = 0; q < Q_; q++) acc += WB[q*R_ + r] * I[q*NN_ + nn];
            g_Acat[(s*R_ + r)*K2_ + n] = acc;
        }
        return;
    }

    // ---------- MLP branch ----------
    float* Ha = sm;                       // [128][ASTRIDE]
    float* Hb = sm + H_*ASTRIDE;          // [128][ASTRIDE]
    __shared__ float xs[PPB][2];

    const int p0 = blockIdx.x * PPB;
    ((float*)xs)[tid] = nodes[p0*2 + tid];       // 128 floats
    __syncthreads();

    // layer 1: [64 pts] x [128 out]
    for (int idx = tid; idx < H_*PPB; idx += 128){
        int j = idx >> 6, p = idx & 63;
        float pre = xs[p][0]*__ldg(&W1[j]) + xs[p][1]*__ldg(&W1[H_ + j]) + __ldg(&b1[j]);
        Ha[j*ASTRIDE + p] = fast_tanh(pre);
    }
    __syncthreads();

    gemm_layer64(Ha, Hb, W2, b2);  __syncthreads();
    gemm_layer64(Hb, Ha, W3, b3);  __syncthreads();

    // layer 4 + (cx, cy) scale, scatter into evcat
    if (tid < PPB){
        float acc = 0.f;
        #pragma unroll 8
        for (int k = 0; k < H_; k++) acc += Ha[k*ASTRIDE + tid] * __ldg(&W4[k]);
        float ev = acc + __ldg(&b4[0]);
        int p = p0 + tid;
        int e = p / NN_, n = p - e*NN_;
        float c00 = __ldg(&BDD[e*4 + 0]), c01 = __ldg(&BDD[e*4 + 1]);
        float c10 = __ldg(&BDD[e*4 + 2]), c11 = __ldg(&BDD[e*4 + 3]);
        g_evcat[e*K2_ + n]       = (c00 + c10) * ev;
        g_evcat[e*K2_ + NN_ + n] = (c01 + c11) * ev;
    }
}

// ============================================================
// Stage 2: 64x128 tiles of u = -J*(evcat @ Acat^T), fused loss,
//          deterministic last-block final reduction.
// ============================================================
__global__ __launch_bounds__(128, 3)
void gemm_loss(const float* __restrict__ J, const float* __restrict__ F,
               float* __restrict__ out){
    extern __shared__ float sm[];
    float* As = sm;                    // [72][ASTRIDE]  (k-major, m fastest)
    float* Bs = sm + K2_*ASTRIDE;      // [72][BSTRIDE]
    const int tid = threadIdx.x;
    const int m0g = blockIdx.y * 64, n0g = blockIdx.x * 128;

    for (int idx = tid; idx < 64*K2_; idx += 128){
        int m = idx / K2_, k = idx - m*K2_;
        As[k*ASTRIDE + m] = g_evcat[(m0g + m)*K2_ + k];
    }
    for (int idx = tid; idx < 128*K2_; idx += 128){
        int n = idx / K2_, k = idx - n*K2_;
        Bs[k*BSTRIDE + n] = g_Acat[(n0g + n)*K2_ + k];
    }
    __syncthreads();

    const int tx = tid & 15, ty = tid >> 4;
    const int m0 = ty * 8, n0 = tx * 8;

    u64t acc[8][4];
    #pragma unroll
    for (int i = 0; i < 8; i++)
        #pragma unroll
        for (int jp = 0; jp < 4; jp++) acc[i][jp] = 0ULL;

    #pragma unroll 4
    for (int k = 0; k < K2_; k++){
        float4 a0 = *(const float4*)(As + k*ASTRIDE + m0);
        float4 a1 = *(const float4*)(As + k*ASTRIDE + m0 + 4);
        F4U b0, b1;
        b0.f = *(const float4*)(Bs + k*BSTRIDE + n0);
        b1.f = *(const float4*)(Bs + k*BSTRIDE + n0 + 4);
        u64t bv[4] = { b0.u[0], b0.u[1], b1.u[0], b1.u[1] };
        float av[8] = { a0.x, a0.y, a0.z, a0.w, a1.x, a1.y, a1.z, a1.w };
        #pragma unroll
        for (int i = 0; i < 8; i++){
            u64t ad = pk2(av[i], av[i]);
            #pragma unroll
            for (int jp = 0; jp < 4; jp++) acc[i][jp] = fma2(ad, bv[jp], acc[i][jp]);
        }
    }

    // fused epilogue
    float lsum = 0.f;
    #pragma unroll
    for (int i = 0; i < 8; i++){
        int e = m0g + m0 + i;
        #pragma unroll
        for (int jp = 0; jp < 4; jp++){
            float lo, hi; upk2(acc[i][jp], lo, hi);
            int n = n0g + n0 + 2*jp;
            float j0 = __ldg(&J[e*S_ + (n    )/R_]);
            float j1 = __ldg(&J[e*S_ + (n + 1)/R_]);
            float r0 = -j0*lo - __ldg(&F[e*SR_ + n    ]);
            float r1 = -j1*hi - __ldg(&F[e*SR_ + n + 1]);
            lsum += r0*r0 + r1*r1;
        }
    }

    __shared__ float red[128];
    red[tid] = lsum; __syncthreads();
    #pragma unroll
    for (int s = 64; s > 0; s >>= 1){
        if (tid < s) red[tid] += red[tid + s];
        __syncthreads();
    }

    __shared__ unsigned s_last;
    if (tid == 0){
        g_partial[blockIdx.y * GX + blockIdx.x] = red[0];
        __threadfence();
        unsigned t = atomicAdd(&g_count, 1u);
        s_last = (t == NPART - 1u) ? 1u : 0u;
    }
    __syncthreads();

    if (s_last){
        __shared__ double dred[128];
        double s = 0.0;
        for (int i = tid; i < NPART; i += 128) s += (double)g_partial[i];
        dred[tid] = s; __syncthreads();
        #pragma unroll
        for (int k = 64; k > 0; k >>= 1){
            if (tid < k) dred[tid] += dred[tid + k];
            __syncthreads();
        }
        if (tid == 0){
            out[0] = (float)(dred[0] / (double)R_);
            g_count = 0;
        }
    }
}

// ============================================================
extern "C" void kernel_launch(void* const* d_in, const int* in_sizes, int n_in,
                              void* d_out, int out_size){
    const float* nodes = (const float*)d_in[0];
    const float* W1    = (const float*)d_in[1];
    const float* b1    = (const float*)d_in[2];
    const float* W2    = (const float*)d_in[3];
    const float* b2    = (const float*)d_in[4];
    const float* W3    = (const float*)d_in[5];
    const float* b3    = (const float*)d_in[6];
    const float* W4    = (const float*)d_in[7];
    const float* b4    = (const float*)d_in[8];
    const float* Ixx   = (const float*)d_in[9];
    const float* Iyy   = (const float*)d_in[10];
    const float* BDD   = (const float*)d_in[11];
    const float* wq    = (const float*)d_in[12];
    const float* Base  = (const float*)d_in[13];
    const float* J     = (const float*)d_in[14];
    const float* F     = (const float*)d_in[15];

    const int s1_smem   = 2 * H_ * ASTRIDE * 4;                 // 69632 B
    const int gemm_smem = (K2_*ASTRIDE + K2_*BSTRIDE) * 4;      // 57600 B
    cudaFuncSetAttribute(stage1,    cudaFuncAttributeMaxDynamicSharedMemorySize, s1_smem);
    cudaFuncSetAttribute(gemm_loss, cudaFuncAttributeMaxDynamicSharedMemorySize, gemm_smem);

    stage1<<<STAGE1_BLOCKS, 128, s1_smem>>>(nodes, W1, b1, W2, b2, W3, b3, W4, b4,
                                            BDD, Ixx, Iyy, wq, Base);
    gemm_loss<<<dim3(GX, GY), 128, gemm_smem>>>(J, F, (float*)d_out);
}